// round 2
// baseline (speedup 1.0000x reference)
#include <cuda_runtime.h>

// Problem shape (fixed by reference setup_inputs: B=32, S=4096, D=256, fp32)
#define BB   32
#define SS   4096
#define DD   256
#define SD4  (SS * DD / 4)   // float4 elements per batch row = 262144
#define KCH  64              // chunks per row for the partial-stats pass

__device__ float2 g_partials[BB * KCH];
__device__ float2 g_stats[BB];   // (mean, inv_std) per batch row

// ---------------------------------------------------------------------------
// Kernel A: per-(row, chunk) partial sum / sumsq over the VALID region only.
// grid = BB*KCH blocks, 256 threads. float4 loads (lens*D divisible by 4).
// ---------------------------------------------------------------------------
__global__ void __launch_bounds__(256)
setnorm_partials(const float4* __restrict__ x, const int* __restrict__ lens) {
    const int b = blockIdx.x / KCH;
    const int k = blockIdx.x % KCH;
    const int n4 = __ldg(&lens[b]) * (DD / 4);   // valid float4 count in row b
    const int chunk = (n4 + KCH - 1) / KCH;
    const int start = k * chunk;
    const int end   = min(start + chunk, n4);

    const float4* row = x + (size_t)b * SD4;

    float s = 0.0f, sq = 0.0f;
    for (int j = start + threadIdx.x; j < end; j += 256) {
        float4 v = row[j];
        s  += (v.x + v.y) + (v.z + v.w);
        sq += (v.x * v.x + v.y * v.y) + (v.z * v.z + v.w * v.w);
    }

    #pragma unroll
    for (int o = 16; o > 0; o >>= 1) {
        s  += __shfl_down_sync(0xffffffffu, s,  o);
        sq += __shfl_down_sync(0xffffffffu, sq, o);
    }
    __shared__ float2 sm[8];
    const int wid = threadIdx.x >> 5, lid = threadIdx.x & 31;
    if (lid == 0) sm[wid] = make_float2(s, sq);
    __syncthreads();
    if (threadIdx.x == 0) {
        float2 acc = sm[0];
        #pragma unroll
        for (int w = 1; w < 8; w++) { acc.x += sm[w].x; acc.y += sm[w].y; }
        g_partials[blockIdx.x] = acc;
    }
}

// ---------------------------------------------------------------------------
// Kernel B: reduce KCH partials per row -> (mean, inv_std). 32 blocks x 32 thr.
// ---------------------------------------------------------------------------
__global__ void __launch_bounds__(32)
setnorm_stats(const int* __restrict__ lens) {
    const int b = blockIdx.x;
    const int t = threadIdx.x;
    float s = 0.0f, sq = 0.0f;
    for (int k = t; k < KCH; k += 32) {
        float2 p = g_partials[b * KCH + k];
        s += p.x; sq += p.y;
    }
    #pragma unroll
    for (int o = 16; o > 0; o >>= 1) {
        s  += __shfl_down_sync(0xffffffffu, s,  o);
        sq += __shfl_down_sync(0xffffffffu, sq, o);
    }
    if (t == 0) {
        float cnt  = fmaxf((float)__ldg(&lens[b]) * (float)DD, 1.0f);
        float mean = s / cnt;
        float var  = fmaxf(sq / cnt - mean * mean, 0.0f);
        g_stats[b] = make_float2(mean, rsqrtf(var + 1e-5f));
    }
}

// ---------------------------------------------------------------------------
// Kernel C: normalize valid positions, write zeros for padding (no x load
// for padding -> saves read bandwidth). grid-stride over (row, float4 idx).
// ---------------------------------------------------------------------------
__global__ void __launch_bounds__(256)
setnorm_apply(const float4* __restrict__ x, const int* __restrict__ lens,
              float4* __restrict__ out) {
    const int b  = blockIdx.y;
    const int n4 = __ldg(&lens[b]) * (DD / 4);   // valid float4 count
    const float2 st = g_stats[b];
    const float mean = st.x, inv = st.y;
    const float4* xr = x   + (size_t)b * SD4;
    float4*       orow = out + (size_t)b * SD4;

    for (int i = blockIdx.x * 256 + threadIdx.x; i < SD4; i += gridDim.x * 256) {
        if (i < n4) {
            float4 v = xr[i];
            float4 o;
            o.x = (v.x - mean) * inv;
            o.y = (v.y - mean) * inv;
            o.z = (v.z - mean) * inv;
            o.w = (v.w - mean) * inv;
            orow[i] = o;
        } else {
            orow[i] = make_float4(0.f, 0.f, 0.f, 0.f);
        }
    }
}

extern "C" void kernel_launch(void* const* d_in, const int* in_sizes, int n_in,
                              void* d_out, int out_size) {
    const float4* x   = (const float4*)d_in[0];
    const int*   lens = (const int*)d_in[1];
    float4*      out  = (float4*)d_out;

    setnorm_partials<<<BB * KCH, 256>>>(x, lens);
    setnorm_stats<<<BB, 32>>>(lens);
    dim3 gridC(SD4 / 256, BB);   // 1024 x 32 blocks
    setnorm_apply<<<gridC, 256>>>(x, lens, out);
}